// round 1
// baseline (speedup 1.0000x reference)
#include <cuda_runtime.h>
#include <math.h>

#define Bn   8
#define Sn   1024
#define Dn   64
#define NHn  4
#define HEn  8            // 2*NH
#define BSn  (Bn*Sn)      // 8192
#define CW   (HEn*Dn)     // 512 (ctx width)

// ---------------- scratch (no allocation allowed) ----------------
__device__ float g_qxp [Bn*Sn*Dn];       // (B,S,D) qx + pos
__device__ float g_kvxp[Bn*Sn*Dn];       // (B,S,D) kvx + pos
__device__ float g_q   [Bn*HEn*Sn*Dn];   // (B,8,S,D)
__device__ float g_k   [Bn*HEn*Sn*Dn];
__device__ float g_v   [Bn*HEn*Sn*Dn];
__device__ float g_ctx [Bn*Sn*CW];       // (B,S,512)

// ---------------- 1) add positional table ----------------
__global__ void add_pos_kernel(const float* __restrict__ qx,
                               const float* __restrict__ kvx,
                               const float* __restrict__ pos) {
    int i = blockIdx.x * blockDim.x + threadIdx.x;
    if (i >= Bn*Sn*Dn) return;
    int sd = i % (Sn*Dn);
    float p = pos[sd];
    g_qxp[i]  = qx[i]  + p;
    g_kvxp[i] = kvx[i] + p;
}

// ---------------- 2) projection: y = x @ W + b, written head-major ----------------
// x: (BS,64) selected by srcSel; W: (64, nh*64); dst: (B, HE, S, D) at head offset h0
// 64x64 output tile, full K=64 in smem, 4x4 register blocking, 256 threads.
__global__ void proj_kernel(const float* __restrict__ W,
                            const float* __restrict__ bias,
                            int srcSel, int dstSel, int nh, int h0) {
    const float* x  = srcSel ? g_kvxp : g_qxp;
    float* dst = (dstSel == 0) ? g_q : (dstSel == 1) ? g_k : g_v;
    const int N = nh * Dn;

    __shared__ float As[64][65];
    __shared__ float Ws[64][65];
    int tid = threadIdx.x;
    int tx = tid & 15, ty = tid >> 4;
    int m0 = blockIdx.y * 64, n0 = blockIdx.x * 64;

    #pragma unroll
    for (int e = 0; e < 16; e++) {
        int idx = e * 256 + tid;
        int r = idx >> 6, c = idx & 63;
        As[r][c] = x[(m0 + r) * 64 + c];
        Ws[r][c] = W[r * N + n0 + c];
    }
    __syncthreads();

    float acc[4][4];
    #pragma unroll
    for (int ci = 0; ci < 4; ci++) {
        float bv = bias[n0 + tx + 16 * ci];
        #pragma unroll
        for (int ri = 0; ri < 4; ri++) acc[ri][ci] = bv;
    }
    #pragma unroll
    for (int k = 0; k < 64; k++) {
        float a[4], b2[4];
        #pragma unroll
        for (int ri = 0; ri < 4; ri++) a[ri]  = As[ty + 16 * ri][k];
        #pragma unroll
        for (int ci = 0; ci < 4; ci++) b2[ci] = Ws[k][tx + 16 * ci];
        #pragma unroll
        for (int ri = 0; ri < 4; ri++)
            #pragma unroll
            for (int ci = 0; ci < 4; ci++)
                acc[ri][ci] += a[ri] * b2[ci];
    }
    #pragma unroll
    for (int ri = 0; ri < 4; ri++)
        #pragma unroll
        for (int ci = 0; ci < 4; ci++) {
            int m = m0 + ty + 16 * ri;      // b*S + s
            int n = n0 + tx + 16 * ci;      // h*64 + d
            int b = m >> 10, s = m & 1023;
            int h = n >> 6,  d = n & 63;
            dst[((size_t)(b * HEn + h0 + h) * Sn + s) * Dn + d] = acc[ri][ci];
        }
}

// ---------------- 3) scores = (q @ k^T) * scale ----------------
// per (b,h): (1024x64) @ (1024x64)^T, 64x64 tile, K=64 fully resident.
__global__ void scores_kernel(float* __restrict__ attn) {
    int bh = blockIdx.z;
    const float* qb = g_q + (size_t)bh * Sn * Dn;
    const float* kb = g_k + (size_t)bh * Sn * Dn;
    float* cb = attn + (size_t)bh * Sn * Sn;

    __shared__ float Qs[64][65];
    __shared__ float Ks[64][65];
    int tid = threadIdx.x;
    int tx = tid & 15, ty = tid >> 4;
    int i0 = blockIdx.y * 64, j0 = blockIdx.x * 64;

    #pragma unroll
    for (int e = 0; e < 16; e++) {
        int idx = e * 256 + tid;
        int r = idx >> 6, c = idx & 63;
        Qs[r][c] = qb[(i0 + r) * Dn + c];
        Ks[r][c] = kb[(j0 + r) * Dn + c];
    }
    __syncthreads();

    float acc[4][4] = {};
    #pragma unroll
    for (int k = 0; k < 64; k++) {
        float a[4], b2[4];
        #pragma unroll
        for (int ri = 0; ri < 4; ri++) a[ri]  = Qs[ty + 16 * ri][k];
        #pragma unroll
        for (int ci = 0; ci < 4; ci++) b2[ci] = Ks[tx + 16 * ci][k];
        #pragma unroll
        for (int ri = 0; ri < 4; ri++)
            #pragma unroll
            for (int ci = 0; ci < 4; ci++)
                acc[ri][ci] += a[ri] * b2[ci];
    }
    #pragma unroll
    for (int ri = 0; ri < 4; ri++)
        #pragma unroll
        for (int ci = 0; ci < 4; ci++)
            cb[(size_t)(i0 + ty + 16 * ri) * Sn + (j0 + tx + 16 * ci)] =
                acc[ri][ci] * 0.125f;
}

// ---------------- 4) softmax over rows of length 1024 ----------------
__global__ void softmax_kernel(float* __restrict__ attn) {
    float* p = attn + (size_t)blockIdx.x * Sn;
    int t = threadIdx.x;
    __shared__ float red[256];

    float v[4];
    float m = -INFINITY;
    #pragma unroll
    for (int e = 0; e < 4; e++) { v[e] = p[t + e * 256]; m = fmaxf(m, v[e]); }
    red[t] = m; __syncthreads();
    for (int s2 = 128; s2 > 0; s2 >>= 1) {
        if (t < s2) red[t] = fmaxf(red[t], red[t + s2]);
        __syncthreads();
    }
    m = red[0]; __syncthreads();

    float sum = 0.f;
    #pragma unroll
    for (int e = 0; e < 4; e++) { v[e] = __expf(v[e] - m); sum += v[e]; }
    red[t] = sum; __syncthreads();
    for (int s2 = 128; s2 > 0; s2 >>= 1) {
        if (t < s2) red[t] += red[t + s2];
        __syncthreads();
    }
    float inv = 1.0f / red[0];
    #pragma unroll
    for (int e = 0; e < 4; e++) p[t + e * 256] = v[e] * inv;
}

// ---------------- 5) ctx = attn @ v, written (B,S,8*64) ----------------
// per (b,h): (1024x1024) @ (1024x64), 64-row x 64-col tile, K chunks of 16.
__global__ void ctx_kernel(const float* __restrict__ attn) {
    int bh = blockIdx.z;
    int b = bh >> 3, h = bh & 7;
    const float* ab = attn + (size_t)bh * Sn * Sn;
    const float* vb = g_v  + (size_t)bh * Sn * Dn;

    __shared__ float As[64][17];
    __shared__ float Bs[16][65];
    int tid = threadIdx.x;
    int tx = tid & 15, ty = tid >> 4;
    int i0 = blockIdx.y * 64;

    float acc[4][4] = {};
    for (int kt = 0; kt < Sn; kt += 16) {
        #pragma unroll
        for (int e = 0; e < 4; e++) {
            int idx = e * 256 + tid;
            { int r = idx >> 4, c = idx & 15; As[r][c] = ab[(size_t)(i0 + r) * Sn + kt + c]; }
            { int r = idx >> 6, c = idx & 63; Bs[r][c] = vb[(kt + r) * Dn + c]; }
        }
        __syncthreads();
        #pragma unroll
        for (int k = 0; k < 16; k++) {
            float a[4], b2[4];
            #pragma unroll
            for (int ri = 0; ri < 4; ri++) a[ri]  = As[ty + 16 * ri][k];
            #pragma unroll
            for (int ci = 0; ci < 4; ci++) b2[ci] = Bs[k][tx + 16 * ci];
            #pragma unroll
            for (int ri = 0; ri < 4; ri++)
                #pragma unroll
                for (int ci = 0; ci < 4; ci++)
                    acc[ri][ci] += a[ri] * b2[ci];
        }
        __syncthreads();
    }
    #pragma unroll
    for (int ri = 0; ri < 4; ri++)
        #pragma unroll
        for (int ci = 0; ci < 4; ci++) {
            int s = i0 + ty + 16 * ri;
            int d = tx + 16 * ci;
            g_ctx[((size_t)(b * Sn + s)) * CW + h * Dn + d] = acc[ri][ci];
        }
}

// ---------------- 6) out = ctx @ Wo + bo ----------------
// (8192x512) @ (512x64): 64-row tile, K chunks of 16.
__global__ void outproj_kernel(const float* __restrict__ Wo,
                               const float* __restrict__ bo,
                               float* __restrict__ out) {
    __shared__ float As[64][17];
    __shared__ float Bs[16][65];
    int tid = threadIdx.x;
    int tx = tid & 15, ty = tid >> 4;
    int m0 = blockIdx.y * 64;

    float acc[4][4];
    #pragma unroll
    for (int ci = 0; ci < 4; ci++) {
        float bv = bo[tx + 16 * ci];
        #pragma unroll
        for (int ri = 0; ri < 4; ri++) acc[ri][ci] = bv;
    }
    for (int kt = 0; kt < CW; kt += 16) {
        #pragma unroll
        for (int e = 0; e < 4; e++) {
            int idx = e * 256 + tid;
            { int r = idx >> 4, c = idx & 15; As[r][c] = g_ctx[(size_t)(m0 + r) * CW + kt + c]; }
            { int r = idx >> 6, c = idx & 63; Bs[r][c] = Wo[(kt + r) * Dn + c]; }
        }
        __syncthreads();
        #pragma unroll
        for (int k = 0; k < 16; k++) {
            float a[4], b2[4];
            #pragma unroll
            for (int ri = 0; ri < 4; ri++) a[ri]  = As[ty + 16 * ri][k];
            #pragma unroll
            for (int ci = 0; ci < 4; ci++) b2[ci] = Bs[k][tx + 16 * ci];
            #pragma unroll
            for (int ri = 0; ri < 4; ri++)
                #pragma unroll
                for (int ci = 0; ci < 4; ci++)
                    acc[ri][ci] += a[ri] * b2[ci];
        }
        __syncthreads();
    }
    #pragma unroll
    for (int ri = 0; ri < 4; ri++)
        #pragma unroll
        for (int ci = 0; ci < 4; ci++)
            out[(size_t)(m0 + ty + 16 * ri) * Dn + tx + 16 * ci] = acc[ri][ci];
}

// ---------------- launch ----------------
extern "C" void kernel_launch(void* const* d_in, const int* in_sizes, int n_in,
                              void* d_out, int out_size) {
    const float* kvx  = (const float*)d_in[0];
    const float* qx   = (const float*)d_in[1];
    const float* pos  = (const float*)d_in[2];
    const float* Wq   = (const float*)d_in[3];
    const float* bq   = (const float*)d_in[4];
    const float* Wka  = (const float*)d_in[5];
    const float* bka  = (const float*)d_in[6];
    const float* Wva  = (const float*)d_in[7];
    const float* bva  = (const float*)d_in[8];
    const float* Wksa = (const float*)d_in[9];
    const float* bksa = (const float*)d_in[10];
    const float* Wvsa = (const float*)d_in[11];
    const float* bvsa = (const float*)d_in[12];
    const float* Wo   = (const float*)d_in[13];
    const float* bo   = (const float*)d_in[14];

    float* out  = (float*)d_out;                 // (B,H,W,D) = 524288 floats
    float* attn = out + (size_t)Bn * Sn * Dn;    // (B,8,S,S) = 67108864 floats

    add_pos_kernel<<<(Bn*Sn*Dn + 255) / 256, 256>>>(qx, kvx, pos);

    // projections (head-major writes)
    proj_kernel<<<dim3(8, BSn/64), 256>>>(Wq,   bq,   0, 0, HEn, 0);  // q   from qxp
    proj_kernel<<<dim3(4, BSn/64), 256>>>(Wka,  bka,  1, 1, NHn, 0);  // ka  from kvxp -> k[0:4]
    proj_kernel<<<dim3(4, BSn/64), 256>>>(Wksa, bksa, 0, 1, NHn, 4);  // ksa from qxp  -> k[4:8]
    proj_kernel<<<dim3(4, BSn/64), 256>>>(Wva,  bva,  1, 2, NHn, 0);  // va  from kvxp -> v[0:4]
    proj_kernel<<<dim3(4, BSn/64), 256>>>(Wvsa, bvsa, 0, 2, NHn, 4);  // vsa from qxp  -> v[4:8]

    scores_kernel <<<dim3(Sn/64, Sn/64, Bn*HEn), 256>>>(attn);
    softmax_kernel<<<Bn*HEn*Sn, 256>>>(attn);
    ctx_kernel    <<<dim3(1, Sn/64, Bn*HEn), 256>>>(attn);
    outproj_kernel<<<dim3(1, BSn/64), 256>>>(Wo, bo, out);
}

// round 2
// speedup vs baseline: 1.3066x; 1.3066x over previous
#include <cuda_runtime.h>
#include <math.h>

#define Bn   8
#define Sn   1024
#define Dn   64
#define NHn  4
#define HEn  8            // 2*NH
#define BSn  (Bn*Sn)      // 8192
#define CW   (HEn*Dn)     // 512

// ---------------- scratch (no allocation allowed) ----------------
__device__ float g_qxp [Bn*Sn*Dn];
__device__ float g_kvxp[Bn*Sn*Dn];
__device__ float g_q   [Bn*HEn*Sn*Dn];   // (B,8,S,D)
__device__ float g_k   [Bn*HEn*Sn*Dn];
__device__ float g_v   [Bn*HEn*Sn*Dn];
__device__ float g_ctx [Bn*Sn*CW];       // (B,S,512)

// ---------------- helpers ----------------
__device__ __forceinline__ unsigned f2tf(float x) {
    unsigned r;
    asm("cvt.rna.tf32.f32 %0, %1;" : "=r"(r) : "f"(x));
    return r;
}

__device__ __forceinline__ void mma8(float* d, const unsigned* a, const unsigned* b) {
    asm volatile(
        "mma.sync.aligned.m16n8k8.row.col.f32.tf32.tf32.f32 "
        "{%0,%1,%2,%3}, {%4,%5,%6,%7}, {%8,%9}, {%0,%1,%2,%3};\n"
        : "+f"(d[0]), "+f"(d[1]), "+f"(d[2]), "+f"(d[3])
        : "r"(a[0]), "r"(a[1]), "r"(a[2]), "r"(a[3]), "r"(b[0]), "r"(b[1]));
}

// ---------------- 1) add positional table ----------------
__global__ void add_pos_kernel(const float* __restrict__ qx,
                               const float* __restrict__ kvx,
                               const float* __restrict__ pos) {
    int i = blockIdx.x * blockDim.x + threadIdx.x;
    if (i >= Bn*Sn*Dn) return;
    int sd = i % (Sn*Dn);
    float p = pos[sd];
    g_qxp[i]  = qx[i]  + p;
    g_kvxp[i] = kvx[i] + p;
}

// ---------------- 2) all projections in ONE launch ----------------
// blockIdx.x selects (matrix, column block); blockIdx.y selects row block.
__global__ void proj_all_kernel(const float* __restrict__ Wq,  const float* __restrict__ bq,
                                const float* __restrict__ Wka, const float* __restrict__ bka,
                                const float* __restrict__ Wva, const float* __restrict__ bva,
                                const float* __restrict__ Wksa,const float* __restrict__ bksa,
                                const float* __restrict__ Wvsa,const float* __restrict__ bvsa) {
    int bx = blockIdx.x;
    const float *W, *bias, *x; float* dst; int N, n0, h0;
    if (bx < 8)       { W=Wq;   bias=bq;   x=g_qxp;  dst=g_q; N=512; n0=bx*64;      h0=0; }
    else if (bx < 12) { W=Wka;  bias=bka;  x=g_kvxp; dst=g_k; N=256; n0=(bx-8)*64;  h0=0; }
    else if (bx < 16) { W=Wksa; bias=bksa; x=g_qxp;  dst=g_k; N=256; n0=(bx-12)*64; h0=4; }
    else if (bx < 20) { W=Wva;  bias=bva;  x=g_kvxp; dst=g_v; N=256; n0=(bx-16)*64; h0=0; }
    else              { W=Wvsa; bias=bvsa; x=g_qxp;  dst=g_v; N=256; n0=(bx-20)*64; h0=4; }

    __shared__ float As[64][65];
    __shared__ float Ws[64][65];
    int tid = threadIdx.x;
    int tx = tid & 15, ty = tid >> 4;
    int m0 = blockIdx.y * 64;

    #pragma unroll
    for (int e = 0; e < 16; e++) {
        int idx = e * 256 + tid;
        int r = idx >> 6, c = idx & 63;
        As[r][c] = x[(m0 + r) * 64 + c];
        Ws[r][c] = W[r * N + n0 + c];
    }
    __syncthreads();

    float acc[4][4];
    #pragma unroll
    for (int ci = 0; ci < 4; ci++) {
        float bv = bias[n0 + tx + 16 * ci];
        #pragma unroll
        for (int ri = 0; ri < 4; ri++) acc[ri][ci] = bv;
    }
    #pragma unroll
    for (int k = 0; k < 64; k++) {
        float a[4], b2[4];
        #pragma unroll
        for (int ri = 0; ri < 4; ri++) a[ri]  = As[ty + 16 * ri][k];
        #pragma unroll
        for (int ci = 0; ci < 4; ci++) b2[ci] = Ws[k][tx + 16 * ci];
        #pragma unroll
        for (int ri = 0; ri < 4; ri++)
            #pragma unroll
            for (int ci = 0; ci < 4; ci++)
                acc[ri][ci] += a[ri] * b2[ci];
    }
    #pragma unroll
    for (int ri = 0; ri < 4; ri++)
        #pragma unroll
        for (int ci = 0; ci < 4; ci++) {
            int m = m0 + ty + 16 * ri;
            int n = n0 + tx + 16 * ci;
            int b = m >> 10, s = m & 1023;
            int h = n >> 6,  d = n & 63;
            dst[((size_t)(b * HEn + h0 + h) * Sn + s) * Dn + d] = acc[ri][ci];
        }
}

// ---------------- 3) scores = (q @ k^T) * scale, tf32 tensor cores ----------------
// 128x128 tile per block, K=64 fully resident in fragment-order smem.
__global__ void __launch_bounds__(256) scores_kernel(float* __restrict__ attn) {
    extern __shared__ unsigned sh[];
    unsigned* Qf = sh;          // [8 mt][8 ks][32 lane][4 reg] = 8192
    unsigned* Kf = sh + 8192;   // [16 nt][8 ks][32 lane][2 reg] = 8192

    int bh = blockIdx.z;
    const float* qb = g_q + (size_t)bh * Sn * Dn;
    const float* kb = g_k + (size_t)bh * Sn * Dn;
    float* cb = attn + (size_t)bh * Sn * Sn;

    int tid = threadIdx.x;
    int i0 = blockIdx.y * 128, j0 = blockIdx.x * 128;

    #pragma unroll
    for (int e = 0; e < 8; e++) {
        int lin = e * 256 + tid;          // 0..2047
        int r = lin >> 4, c4 = lin & 15;  // r: 0..127, 16 float4 per row
        float4 v = *(const float4*)&qb[(size_t)(i0 + r) * 64 + c4 * 4];
        int mt = r >> 4, rr = r & 15, g = rr & 7, hi = rr >> 3;
        float va[4] = {v.x, v.y, v.z, v.w};
        #pragma unroll
        for (int j = 0; j < 4; j++) {
            int c = c4 * 4 + j;
            int ks = c >> 3, cc = c & 7;
            int lane = (g << 2) | (cc & 3);
            int reg = hi | ((cc >> 2) << 1);
            Qf[((mt * 8 + ks) * 32 + lane) * 4 + reg] = f2tf(va[j]);
        }
        float4 w = *(const float4*)&kb[(size_t)(j0 + r) * 64 + c4 * 4];
        int nt = r >> 3, g2 = r & 7;
        float wa[4] = {w.x, w.y, w.z, w.w};
        #pragma unroll
        for (int j = 0; j < 4; j++) {
            int c = c4 * 4 + j;
            int ks = c >> 3, kk = c & 7;
            int lane = (g2 << 2) | (kk & 3);
            int reg = kk >> 2;
            Kf[((nt * 8 + ks) * 32 + lane) * 2 + reg] = f2tf(wa[j]);
        }
    }
    __syncthreads();

    int wid = tid >> 5, lane = tid & 31;
    int wm = wid >> 2, wn = wid & 3;   // warp tile: 64 rows x 32 cols

    float acc[4][4][4] = {};
    #pragma unroll
    for (int ks = 0; ks < 8; ks++) {
        unsigned a[4][4], b[4][2];
        #pragma unroll
        for (int i = 0; i < 4; i++)
            *(uint4*)a[i] = *(const uint4*)&Qf[(((wm * 4 + i) * 8 + ks) * 32 + lane) * 4];
        #pragma unroll
        for (int j = 0; j < 4; j++)
            *(uint2*)b[j] = *(const uint2*)&Kf[(((wn * 4 + j) * 8 + ks) * 32 + lane) * 2];
        #pragma unroll
        for (int i = 0; i < 4; i++)
            #pragma unroll
            for (int j = 0; j < 4; j++)
                mma8(acc[i][j], a[i], b[j]);
    }

    int g = lane >> 2, tig = lane & 3;
    #pragma unroll
    for (int i = 0; i < 4; i++)
        #pragma unroll
        for (int j = 0; j < 4; j++) {
            int row = i0 + (wm * 4 + i) * 16 + g;
            int col = j0 + (wn * 4 + j) * 8 + 2 * tig;
            float2 lo = {acc[i][j][0] * 0.125f, acc[i][j][1] * 0.125f};
            float2 hi = {acc[i][j][2] * 0.125f, acc[i][j][3] * 0.125f};
            *(float2*)&cb[(size_t)row * Sn + col] = lo;
            *(float2*)&cb[(size_t)(row + 8) * Sn + col] = hi;
        }
}

// ---------------- 4) softmax over rows of length 1024 ----------------
__global__ void softmax_kernel(float* __restrict__ attn) {
    float* p = attn + (size_t)blockIdx.x * Sn;
    int t = threadIdx.x;  // 256
    __shared__ float sm[8], ss[8];

    float4 v = ((float4*)p)[t];
    float m = fmaxf(fmaxf(v.x, v.y), fmaxf(v.z, v.w));
    #pragma unroll
    for (int o = 16; o > 0; o >>= 1) m = fmaxf(m, __shfl_xor_sync(~0u, m, o));
    if ((t & 31) == 0) sm[t >> 5] = m;
    __syncthreads();
    m = sm[0];
    #pragma unroll
    for (int w = 1; w < 8; w++) m = fmaxf(m, sm[w]);

    v.x = __expf(v.x - m); v.y = __expf(v.y - m);
    v.z = __expf(v.z - m); v.w = __expf(v.w - m);
    float sum = v.x + v.y + v.z + v.w;
    #pragma unroll
    for (int o = 16; o > 0; o >>= 1) sum += __shfl_xor_sync(~0u, sum, o);
    if ((t & 31) == 0) ss[t >> 5] = sum;
    __syncthreads();
    sum = 0.f;
    #pragma unroll
    for (int w = 0; w < 8; w++) sum += ss[w];
    float inv = 1.0f / sum;

    v.x *= inv; v.y *= inv; v.z *= inv; v.w *= inv;
    ((float4*)p)[t] = v;
}

// ---------------- 5) ctx = attn @ v, tf32 tensor cores ----------------
// 64-row x 64-col tile per block; K loop in chunks of 64.
__global__ void __launch_bounds__(256) ctx_kernel(const float* __restrict__ attn) {
    __shared__ unsigned Af[4 * 8 * 32 * 4];  // [4 mt][8 ks][32][4] = 16KB
    __shared__ unsigned Bf[8 * 8 * 32 * 2];  // [8 nt][8 ks][32][2] = 16KB

    int bh = blockIdx.y;
    int b = bh >> 3, h = bh & 7;
    const float* ab = attn + (size_t)bh * Sn * Sn;
    const float* vb = g_v  + (size_t)bh * Sn * Dn;

    int tid = threadIdx.x;
    int m0 = blockIdx.x * 64;
    int wid = tid >> 5, lane = tid & 31;
    int wm = wid >> 2, wn = wid & 3;   // warp tile: 32 rows x 16 cols

    float acc[2][2][4] = {};

    for (int kt = 0; kt < Sn; kt += 64) {
        #pragma unroll
        for (int e = 0; e < 4; e++) {
            int lin = e * 256 + tid;          // 0..1023
            int r = lin >> 4, c4 = lin & 15;  // attn: r 0..63 rows, c4 0..15
            float4 v = *(const float4*)&ab[(size_t)(m0 + r) * Sn + kt + c4 * 4];
            int mt = r >> 4, rr = r & 15, g = rr & 7, hi = rr >> 3;
            float va[4] = {v.x, v.y, v.z, v.w};
            #pragma unroll
            for (int j = 0; j < 4; j++) {
                int c = c4 * 4 + j;
                int ks = c >> 3, cc = c & 7;
                int ln = (g << 2) | (cc & 3);
                int reg = hi | ((cc >> 2) << 1);
                Af[((mt * 8 + ks) * 32 + ln) * 4 + reg] = f2tf(va[j]);
            }
            // v tile: rows = k (kk), cols = n(d)
            int kk = r;
            float4 w = *(const float4*)&vb[(size_t)(kt + kk) * 64 + c4 * 4];
            int ks2 = kk >> 3, r8 = kk & 7;
            float wa[4] = {w.x, w.y, w.z, w.w};
            #pragma unroll
            for (int j = 0; j < 4; j++) {
                int n = c4 * 4 + j;
                int nt = n >> 3, gn = n & 7;
                int ln = (gn << 2) | (r8 & 3);
                int reg = r8 >> 2;
                Bf[((nt * 8 + ks2) * 32 + ln) * 2 + reg] = f2tf(wa[j]);
            }
        }
        __syncthreads();

        #pragma unroll
        for (int ks = 0; ks < 8; ks++) {
            unsigned a[2][4], bfr[2][2];
            #pragma unroll
            for (int i = 0; i < 2; i++)
                *(uint4*)a[i] = *(const uint4*)&Af[(((wm * 2 + i) * 8 + ks) * 32 + lane) * 4];
            #pragma unroll
            for (int j = 0; j < 2; j++)
                *(uint2*)bfr[j] = *(const uint2*)&Bf[(((wn * 2 + j) * 8 + ks) * 32 + lane) * 2];
            #pragma unroll
            for (int i = 0; i < 2; i++)
                #pragma unroll
                for (int j = 0; j < 2; j++)
                    mma8(acc[i][j], a[i], bfr[j]);
        }
        __syncthreads();
    }

    int g = lane >> 2, tig = lane & 3;
    #pragma unroll
    for (int i = 0; i < 2; i++)
        #pragma unroll
        for (int j = 0; j < 2; j++) {
            int s = m0 + (wm * 2 + i) * 16 + g;
            int d = (wn * 2 + j) * 8 + 2 * tig;
            float2 lo = {acc[i][j][0], acc[i][j][1]};
            float2 hi = {acc[i][j][2], acc[i][j][3]};
            *(float2*)&g_ctx[((size_t)(b * Sn + s)) * CW + h * Dn + d] = lo;
            *(float2*)&g_ctx[((size_t)(b * Sn + s + 8)) * CW + h * Dn + d] = hi;
        }
}

// ---------------- 6) out = ctx @ Wo + bo ----------------
__global__ void outproj_kernel(const float* __restrict__ Wo,
                               const float* __restrict__ bo,
                               float* __restrict__ out) {
    __shared__ float As[64][17];
    __shared__ float Bs[16][65];
    int tid = threadIdx.x;
    int tx = tid & 15, ty = tid >> 4;
    int m0 = blockIdx.y * 64;

    float acc[4][4];
    #pragma unroll
    for (int ci = 0; ci < 4; ci++) {
        float bv = bo[tx + 16 * ci];
        #pragma unroll
        for (int ri = 0; ri < 4; ri++) acc[ri][ci] = bv;
    }
    for (int kt = 0; kt < CW; kt += 16) {
        #pragma unroll
        for (int e = 0; e < 4; e++) {
            int idx = e * 256 + tid;
            { int r = idx >> 4, c = idx & 15; As[r][c] = g_ctx[(size_t)(m0 + r) * CW + kt + c]; }
            { int r = idx >> 6, c = idx & 63; Bs[r][c] = Wo[(kt + r) * Dn + c]; }
        }
        __syncthreads();
        #pragma unroll
        for (int k = 0; k < 16; k++) {
            float a[4], b2[4];
            #pragma unroll
            for (int ri = 0; ri < 4; ri++) a[ri]  = As[ty + 16 * ri][k];
            #pragma unroll
            for (int ci = 0; ci < 4; ci++) b2[ci] = Bs[k][tx + 16 * ci];
            #pragma unroll
            for (int ri = 0; ri < 4; ri++)
                #pragma unroll
                for (int ci = 0; ci < 4; ci++)
                    acc[ri][ci] += a[ri] * b2[ci];
        }
        __syncthreads();
    }
    #pragma unroll
    for (int ri = 0; ri < 4; ri++)
        #pragma unroll
        for (int ci = 0; ci < 4; ci++)
            out[(size_t)(m0 + ty + 16 * ri) * Dn + tx + 16 * ci] = acc[ri][ci];
}

// ---------------- launch ----------------
extern "C" void kernel_launch(void* const* d_in, const int* in_sizes, int n_in,
                              void* d_out, int out_size) {
    const float* kvx  = (const float*)d_in[0];
    const float* qx   = (const float*)d_in[1];
    const float* pos  = (const float*)d_in[2];
    const float* Wq   = (const float*)d_in[3];
    const float* bq   = (const float*)d_in[4];
    const float* Wka  = (const float*)d_in[5];
    const float* bka  = (const float*)d_in[6];
    const float* Wva  = (const float*)d_in[7];
    const float* bva  = (const float*)d_in[8];
    const float* Wksa = (const float*)d_in[9];
    const float* bksa = (const float*)d_in[10];
    const float* Wvsa = (const float*)d_in[11];
    const float* bvsa = (const float*)d_in[12];
    const float* Wo   = (const float*)d_in[13];
    const float* bo   = (const float*)d_in[14];

    float* out  = (float*)d_out;
    float* attn = out + (size_t)Bn * Sn * Dn;

    static bool attr_set = false;
    if (!attr_set) {
        cudaFuncSetAttribute(scores_kernel,
                             cudaFuncAttributeMaxDynamicSharedMemorySize, 65536);
        attr_set = true;
    }

    add_pos_kernel<<<(Bn*Sn*Dn + 255) / 256, 256>>>(qx, kvx, pos);
    proj_all_kernel<<<dim3(24, BSn/64), 256>>>(Wq, bq, Wka, bka, Wva, bva,
                                               Wksa, bksa, Wvsa, bvsa);
    scores_kernel <<<dim3(Sn/128, Sn/128, Bn*HEn), 256, 65536>>>(attn);
    softmax_kernel<<<Bn*HEn*Sn, 256>>>(attn);
    ctx_kernel    <<<dim3(Sn/64, Bn*HEn), 256>>>(attn);
    outproj_kernel<<<dim3(1, BSn/64), 256>>>(Wo, bo, out);
}